// round 5
// baseline (speedup 1.0000x reference)
#include <cuda_runtime.h>
#include <cuda_bf16.h>
#include <cstdint>

#define K_DIM 512
#define N_DIM 512
#define BM 128
#define BN 128
#define M_MAX 65536

// ---------------- scratch (allocation-free) ----------------
__device__ int  g_bqi[N_DIM];                                   // quantized bias (int32)
__device__ __align__(16) char  g_wq[N_DIM * K_DIM];             // w_q as s8, [N][K] K-major
__device__ __align__(16) char  g_xq[(size_t)M_MAX * K_DIM];     // x_q as s8, [M][K]

// ---------------- helpers ----------------
__device__ __forceinline__ uint32_t smem_u32(const void* p) {
    uint32_t a;
    asm("{ .reg .u64 t; cvta.to.shared.u64 t, %1; cvt.u32.u64 %0, t; }" : "=r"(a) : "l"(p));
    return a;
}
__device__ __forceinline__ void cp_async16(uint32_t dst, const void* src) {
    asm volatile("cp.async.cg.shared.global [%0], [%1], 16;" :: "r"(dst), "l"(src) : "memory");
}
__device__ __forceinline__ void ldmatrix_x4(uint32_t* r, uint32_t addr) {
    asm volatile("ldmatrix.sync.aligned.m8n8.x4.shared.b16 {%0,%1,%2,%3}, [%4];"
                 : "=r"(r[0]), "=r"(r[1]), "=r"(r[2]), "=r"(r[3]) : "r"(addr));
}
// D[16x8] += A[16x32] * B[32x8], s8 x s8 -> s32
__device__ __forceinline__ void mma_s8(int* d, const uint32_t* a, uint32_t b0, uint32_t b1) {
    asm volatile("mma.sync.aligned.m16n8k32.row.col.s32.s8.s8.s32 "
                 "{%0,%1,%2,%3}, {%4,%5,%6,%7}, {%8,%9}, {%0,%1,%2,%3};"
                 : "+r"(d[0]), "+r"(d[1]), "+r"(d[2]), "+r"(d[3])
                 : "r"(a[0]), "r"(a[1]), "r"(a[2]), "r"(a[3]), "r"(b0), "r"(b1));
}
__device__ __forceinline__ uint32_t pack4(float a, float b, float c, float d) {
    int ia = __float2int_rn(a), ib = __float2int_rn(b);
    int ic = __float2int_rn(c), id = __float2int_rn(d);
    return (uint32_t)(ia & 255) | ((uint32_t)(ib & 255) << 8) |
           ((uint32_t)(ic & 255) << 16) | ((uint32_t)(id & 255) << 24);
}

// ---------------- x conversion: fp32 -> s8, 16 elems/thread ----------------
__global__ void convert_x(const float* __restrict__ x, int n16) {
    int i = blockIdx.x * blockDim.x + threadIdx.x;
    if (i >= n16) return;
    const float4* p = (const float4*)x + (size_t)i * 4;
    float4 v0 = p[0], v1 = p[1], v2 = p[2], v3 = p[3];
    uint4 u;
    u.x = pack4(v0.x, v0.y, v0.z, v0.w);
    u.y = pack4(v1.x, v1.y, v1.z, v1.w);
    u.z = pack4(v2.x, v2.y, v2.z, v2.w);
    u.w = pack4(v3.x, v3.y, v3.z, v3.w);
    ((uint4*)g_xq)[i] = u;
}

// ---------------- weight quantization (one block per output channel) ----------------
__global__ void quant_weight_kernel(const float* __restrict__ weight,
                                    const float* __restrict__ bias,
                                    const float* __restrict__ scale_x,
                                    float* __restrict__ scale_out_dst,
                                    int write_scale) {
    __shared__ float red[256];
    const int o = blockIdx.x;
    const float* wrow = weight + o * K_DIM;

    float m = 0.0f;
    for (int k = threadIdx.x; k < K_DIM; k += 256) m = fmaxf(m, fabsf(wrow[k]));
    red[threadIdx.x] = m;
    __syncthreads();
    for (int s = 128; s > 0; s >>= 1) {
        if (threadIdx.x < s) red[threadIdx.x] = fmaxf(red[threadIdx.x], red[threadIdx.x + s]);
        __syncthreads();
    }
    const float scale = fmaxf(red[0], 1e-8f) / 127.0f;
    const float inv_scale = 1.0f / scale;

    for (int k = threadIdx.x; k < K_DIM; k += 256) {
        float q = rintf(wrow[k] * inv_scale);             // round-half-even == jnp.round
        q = fminf(fmaxf(q, -128.0f), 127.0f);
        g_wq[o * K_DIM + k] = (char)(int)q;
    }
    if (threadIdx.x == 0) {
        const float so = scale * scale_x[0];
        float bq = rintf(bias[o] / so);
        bq = fminf(fmaxf(bq, -2147483520.0f), 2147483520.0f);
        g_bqi[o] = (int)bq;
        if (write_scale) scale_out_dst[o] = so;
    }
}

// ---------------- IMMA GEMM: C[M,512] = x_s8 * Wq^T + bq ----------------
// 256 threads, 8 warps 2(M)x4(N); warp tile 64x32; 4-stage cp.async, BK=64.
#define STAGE_SZ 8192
#define S_B0     32768
#define S_TOTAL  65536

__global__ __launch_bounds__(256, 1) void gemm_imma(float* __restrict__ C) {
    extern __shared__ __align__(1024) char smem[];
    const uint32_t sb = smem_u32(smem);
    const int tid = threadIdx.x, lane = tid & 31, w = tid >> 5;
    const int wm = w & 1, wn = w >> 1;
    const int mb = blockIdx.y * BM;
    const int nb = blockIdx.x * BN;

    // --- cp.async staging: per stage 128 rows x 64B = 512 x 16B; 2/thread each for A,B
    const int r0 = tid >> 2;
    const int ch = (tid & 3) * 16;
    const uint32_t dA0 = (uint32_t)(r0 * 64)        + (uint32_t)(ch ^ ((r0 * 8) & 0x30));
    const uint32_t dA1 = (uint32_t)((r0 + 64) * 64) + (uint32_t)(ch ^ (((r0 + 64) * 8) & 0x30));
    const char* srcA0 = g_xq + (size_t)(mb + r0) * K_DIM + ch;
    const char* srcA1 = g_xq + (size_t)(mb + r0 + 64) * K_DIM + ch;
    const char* srcB0 = g_wq + (size_t)(nb + r0) * K_DIM + ch;
    const char* srcB1 = g_wq + (size_t)(nb + r0 + 64) * K_DIM + ch;

    // --- fragment lane addressing (64B rows, swizzle (row*8)&0x30)
    const uint32_t afr = wm * 64 + (lane & 15);
    const uint32_t afrx = (afr * 8) & 0x30;
    const uint32_t afkb = (lane >> 4) * 16;
    const uint32_t afbase = sb + afr * 64;
    const uint32_t bfr = wn * 32 + ((lane >> 4) << 3) + (lane & 7);
    const uint32_t bfrx = (bfr * 8) & 0x30;
    const uint32_t bfkb = ((lane >> 3) & 1) * 16;
    const uint32_t bfbase = sb + S_B0 + bfr * 64;

    int acc[4][4][4] = {};

    // prologue: issue stages for chunks 0,1,2
    #pragma unroll
    for (int c = 0; c < 3; c++) {
        const uint32_t so = (uint32_t)c * STAGE_SZ;
        cp_async16(sb + so + dA0, srcA0 + c * 64);
        cp_async16(sb + so + dA1, srcA1 + c * 64);
        cp_async16(sb + S_B0 + so + dA0, srcB0 + c * 64);
        cp_async16(sb + S_B0 + so + dA1, srcB1 + c * 64);
        asm volatile("cp.async.commit_group;" ::: "memory");
    }

    #pragma unroll 1
    for (int c = 0; c < 8; c++) {                 // 8 K-chunks of 64
        if (c < 6)       asm volatile("cp.async.wait_group 2;" ::: "memory");
        else if (c == 6) asm volatile("cp.async.wait_group 1;" ::: "memory");
        else             asm volatile("cp.async.wait_group 0;" ::: "memory");
        __syncthreads();

        if (c < 5) {                               // issue chunk c+3
            const int cn = c + 3;
            const uint32_t so1 = (uint32_t)(cn & 3) * STAGE_SZ;
            cp_async16(sb + so1 + dA0, srcA0 + cn * 64);
            cp_async16(sb + so1 + dA1, srcA1 + cn * 64);
            cp_async16(sb + S_B0 + so1 + dA0, srcB0 + cn * 64);
            cp_async16(sb + S_B0 + so1 + dA1, srcB1 + cn * 64);
            asm volatile("cp.async.commit_group;" ::: "memory");
        }

        const uint32_t so = (uint32_t)(c & 3) * STAGE_SZ;
        #pragma unroll
        for (int kk = 0; kk < 2; kk++) {
            uint32_t af[4][4], bf[2][4];
            #pragma unroll
            for (int mi = 0; mi < 4; mi++)
                ldmatrix_x4(af[mi], afbase + so + mi * 1024 + ((kk * 32 + afkb) ^ afrx));
            #pragma unroll
            for (int pq = 0; pq < 2; pq++)
                ldmatrix_x4(bf[pq], bfbase + so + pq * 1024 + ((kk * 32 + bfkb) ^ bfrx));
            #pragma unroll
            for (int mi = 0; mi < 4; mi++)
                #pragma unroll
                for (int ni = 0; ni < 4; ni++)
                    mma_s8(acc[mi][ni], af[mi],
                           bf[ni >> 1][(ni & 1) * 2], bf[ni >> 1][(ni & 1) * 2 + 1]);
        }
        __syncthreads();
    }

    // ---------------- epilogue: +bias(int), cvt to float, float2 stores
    const int mrow = mb + wm * 64 + (lane >> 2);
    const int ncol = nb + wn * 32 + (lane & 3) * 2;
    #pragma unroll
    for (int ni = 0; ni < 4; ni++) {
        const int2 bq = *(const int2*)&g_bqi[ncol + ni * 8];
        #pragma unroll
        for (int mi = 0; mi < 4; mi++) {
            const int rr = mrow + mi * 16;
            float2 v0 = make_float2((float)(acc[mi][ni][0] + bq.x), (float)(acc[mi][ni][1] + bq.y));
            float2 v1 = make_float2((float)(acc[mi][ni][2] + bq.x), (float)(acc[mi][ni][3] + bq.y));
            *(float2*)(C + (size_t)rr * N_DIM + ncol + ni * 8) = v0;
            *(float2*)(C + (size_t)(rr + 8) * N_DIM + ncol + ni * 8) = v1;
        }
    }
}

// ---------------- launch ----------------
extern "C" void kernel_launch(void* const* d_in, const int* in_sizes, int n_in,
                              void* d_out, int out_size) {
    const float* x_q     = (const float*)d_in[0];   // [M, 512]
    const float* weight  = (const float*)d_in[1];   // [512, 512]
    const float* bias    = (const float*)d_in[2];   // [512]
    const float* scale_x = (const float*)d_in[3];   // [1]
    float* out = (float*)d_out;

    const int M = in_sizes[0] / K_DIM;
    const long long need = (long long)M * N_DIM + N_DIM;
    const int write_scale = ((long long)out_size >= need) ? 1 : 0;

    quant_weight_kernel<<<N_DIM, 256>>>(weight, bias, scale_x,
                                        out + (size_t)M * N_DIM, write_scale);

    const int n16 = M * K_DIM / 16;
    convert_x<<<(n16 + 255) / 256, 256>>>(x_q, n16);

    cudaFuncSetAttribute(gemm_imma, cudaFuncAttributeMaxDynamicSharedMemorySize, S_TOTAL);
    dim3 grid(N_DIM / BN, M / BM);
    gemm_imma<<<grid, 256, S_TOTAL>>>(out);
}

// round 6
// speedup vs baseline: 1.0103x; 1.0103x over previous
#include <cuda_runtime.h>
#include <cuda_bf16.h>
#include <cstdint>

#define K_DIM 512
#define N_DIM 512
#define BM 128
#define BN 128
#define M_MAX 65536

// ---------------- scratch (allocation-free) ----------------
__device__ int  g_bqi[N_DIM];                                   // quantized bias (int32)
__device__ __align__(16) char  g_wq[N_DIM * K_DIM];             // w_q as s8, [N][K] K-major
__device__ __align__(16) char  g_xq[(size_t)M_MAX * K_DIM];     // x_q as s8, [M][K]

// ---------------- helpers ----------------
__device__ __forceinline__ uint32_t smem_u32(const void* p) {
    uint32_t a;
    asm("{ .reg .u64 t; cvta.to.shared.u64 t, %1; cvt.u32.u64 %0, t; }" : "=r"(a) : "l"(p));
    return a;
}
__device__ __forceinline__ void cp_async16(uint32_t dst, const void* src) {
    asm volatile("cp.async.cg.shared.global [%0], [%1], 16;" :: "r"(dst), "l"(src) : "memory");
}
__device__ __forceinline__ void ldmatrix_x4(uint32_t* r, uint32_t addr) {
    asm volatile("ldmatrix.sync.aligned.m8n8.x4.shared.b16 {%0,%1,%2,%3}, [%4];"
                 : "=r"(r[0]), "=r"(r[1]), "=r"(r[2]), "=r"(r[3]) : "r"(addr));
}
// D[16x8] += A[16x32] * B[32x8], s8 x s8 -> s32
__device__ __forceinline__ void mma_s8(int* d, const uint32_t* a, uint32_t b0, uint32_t b1) {
    asm volatile("mma.sync.aligned.m16n8k32.row.col.s32.s8.s8.s32 "
                 "{%0,%1,%2,%3}, {%4,%5,%6,%7}, {%8,%9}, {%0,%1,%2,%3};"
                 : "+r"(d[0]), "+r"(d[1]), "+r"(d[2]), "+r"(d[3])
                 : "r"(a[0]), "r"(a[1]), "r"(a[2]), "r"(a[3]), "r"(b0), "r"(b1));
}
__device__ __forceinline__ uint32_t pack4(float a, float b, float c, float d) {
    int ia = __float2int_rn(a), ib = __float2int_rn(b);
    int ic = __float2int_rn(c), id = __float2int_rn(d);
    return (uint32_t)(ia & 255) | ((uint32_t)(ib & 255) << 8) |
           ((uint32_t)(ic & 255) << 16) | ((uint32_t)(id & 255) << 24);
}

// ---------------- x conversion: fp32 -> s8, 16 elems/thread ----------------
__global__ void convert_x(const float* __restrict__ x, int n16) {
    int i = blockIdx.x * blockDim.x + threadIdx.x;
    if (i >= n16) return;
    const float4* p = (const float4*)x + (size_t)i * 4;
    float4 v0 = p[0], v1 = p[1], v2 = p[2], v3 = p[3];
    uint4 u;
    u.x = pack4(v0.x, v0.y, v0.z, v0.w);
    u.y = pack4(v1.x, v1.y, v1.z, v1.w);
    u.z = pack4(v2.x, v2.y, v2.z, v2.w);
    u.w = pack4(v3.x, v3.y, v3.z, v3.w);
    ((uint4*)g_xq)[i] = u;
}

// ---------------- weight quantization (one block per output channel) ----------------
__global__ void quant_weight_kernel(const float* __restrict__ weight,
                                    const float* __restrict__ bias,
                                    const float* __restrict__ scale_x,
                                    float* __restrict__ scale_out_dst,
                                    int write_scale) {
    __shared__ float red[256];
    const int o = blockIdx.x;
    const float* wrow = weight + o * K_DIM;

    float m = 0.0f;
    for (int k = threadIdx.x; k < K_DIM; k += 256) m = fmaxf(m, fabsf(wrow[k]));
    red[threadIdx.x] = m;
    __syncthreads();
    for (int s = 128; s > 0; s >>= 1) {
        if (threadIdx.x < s) red[threadIdx.x] = fmaxf(red[threadIdx.x], red[threadIdx.x + s]);
        __syncthreads();
    }
    const float scale = fmaxf(red[0], 1e-8f) / 127.0f;
    const float inv_scale = 1.0f / scale;

    for (int k = threadIdx.x; k < K_DIM; k += 256) {
        float q = rintf(wrow[k] * inv_scale);             // round-half-even == jnp.round
        q = fminf(fmaxf(q, -128.0f), 127.0f);
        g_wq[o * K_DIM + k] = (char)(int)q;
    }
    if (threadIdx.x == 0) {
        const float so = scale * scale_x[0];
        float bq = rintf(bias[o] / so);
        bq = fminf(fmaxf(bq, -2147483520.0f), 2147483520.0f);
        g_bqi[o] = (int)bq;
        if (write_scale) scale_out_dst[o] = so;
    }
}

// ---------------- IMMA GEMM: C[M,512] = x_s8 * Wq^T + bq ----------------
// 256 threads, 8 warps 2(M)x4(N); warp tile 64x32; 4-stage cp.async, BK=64.
// __launch_bounds__(256,2): cap 128 regs -> 2 CTAs/SM (latency hiding).
#define STAGE_SZ 8192
#define S_B0     32768
#define S_TOTAL  65536

__global__ __launch_bounds__(256, 2) void gemm_imma(float* __restrict__ C) {
    extern __shared__ __align__(1024) char smem[];
    const uint32_t sb = smem_u32(smem);
    const int tid = threadIdx.x, lane = tid & 31, w = tid >> 5;
    const int wm = w & 1, wn = w >> 1;
    const int mb = blockIdx.y * BM;
    const int nb = blockIdx.x * BN;

    // --- cp.async staging: per stage 128 rows x 64B = 512 x 16B; 2/thread each for A,B
    const int r0 = tid >> 2;
    const int ch = (tid & 3) * 16;
    const uint32_t dA0 = (uint32_t)(r0 * 64)        + (uint32_t)(ch ^ ((r0 * 8) & 0x30));
    const uint32_t dA1 = (uint32_t)((r0 + 64) * 64) + (uint32_t)(ch ^ (((r0 + 64) * 8) & 0x30));
    const char* srcA0 = g_xq + (size_t)(mb + r0) * K_DIM + ch;
    const char* srcA1 = g_xq + (size_t)(mb + r0 + 64) * K_DIM + ch;
    const char* srcB0 = g_wq + (size_t)(nb + r0) * K_DIM + ch;
    const char* srcB1 = g_wq + (size_t)(nb + r0 + 64) * K_DIM + ch;

    // --- fragment lane addressing (64B rows, swizzle (row*8)&0x30)
    const uint32_t afr = wm * 64 + (lane & 15);
    const uint32_t afrx = (afr * 8) & 0x30;
    const uint32_t afkb = (lane >> 4) * 16;
    const uint32_t afbase = sb + afr * 64;
    const uint32_t bfr = wn * 32 + ((lane >> 4) << 3) + (lane & 7);
    const uint32_t bfrx = (bfr * 8) & 0x30;
    const uint32_t bfkb = ((lane >> 3) & 1) * 16;
    const uint32_t bfbase = sb + S_B0 + bfr * 64;

    int acc[4][4][4] = {};

    // prologue: issue stages for chunks 0,1,2
    #pragma unroll
    for (int c = 0; c < 3; c++) {
        const uint32_t so = (uint32_t)c * STAGE_SZ;
        cp_async16(sb + so + dA0, srcA0 + c * 64);
        cp_async16(sb + so + dA1, srcA1 + c * 64);
        cp_async16(sb + S_B0 + so + dA0, srcB0 + c * 64);
        cp_async16(sb + S_B0 + so + dA1, srcB1 + c * 64);
        asm volatile("cp.async.commit_group;" ::: "memory");
    }

    #pragma unroll 1
    for (int c = 0; c < 8; c++) {                 // 8 K-chunks of 64
        if (c < 6)       asm volatile("cp.async.wait_group 2;" ::: "memory");
        else if (c == 6) asm volatile("cp.async.wait_group 1;" ::: "memory");
        else             asm volatile("cp.async.wait_group 0;" ::: "memory");
        __syncthreads();   // data visible; also fences stage (c-1) readers before reuse below

        if (c < 5) {                               // issue chunk c+3 into stage (c-1)&3
            const int cn = c + 3;
            const uint32_t so1 = (uint32_t)(cn & 3) * STAGE_SZ;
            cp_async16(sb + so1 + dA0, srcA0 + cn * 64);
            cp_async16(sb + so1 + dA1, srcA1 + cn * 64);
            cp_async16(sb + S_B0 + so1 + dA0, srcB0 + cn * 64);
            cp_async16(sb + S_B0 + so1 + dA1, srcB1 + cn * 64);
            asm volatile("cp.async.commit_group;" ::: "memory");
        }

        const uint32_t so = (uint32_t)(c & 3) * STAGE_SZ;
        #pragma unroll
        for (int kk = 0; kk < 2; kk++) {
            uint32_t af[4][4], bf[2][4];
            #pragma unroll
            for (int mi = 0; mi < 4; mi++)
                ldmatrix_x4(af[mi], afbase + so + mi * 1024 + ((kk * 32 + afkb) ^ afrx));
            #pragma unroll
            for (int pq = 0; pq < 2; pq++)
                ldmatrix_x4(bf[pq], bfbase + so + pq * 1024 + ((kk * 32 + bfkb) ^ bfrx));
            #pragma unroll
            for (int mi = 0; mi < 4; mi++)
                #pragma unroll
                for (int ni = 0; ni < 4; ni++)
                    mma_s8(acc[mi][ni], af[mi],
                           bf[ni >> 1][(ni & 1) * 2], bf[ni >> 1][(ni & 1) * 2 + 1]);
        }
        // no trailing __syncthreads: next iteration's leading barrier orders stage reuse
    }

    // ---------------- epilogue: +bias(int), cvt to float, float2 stores
    const int mrow = mb + wm * 64 + (lane >> 2);
    const int ncol = nb + wn * 32 + (lane & 3) * 2;
    #pragma unroll
    for (int ni = 0; ni < 4; ni++) {
        const int2 bq = *(const int2*)&g_bqi[ncol + ni * 8];
        #pragma unroll
        for (int mi = 0; mi < 4; mi++) {
            const int rr = mrow + mi * 16;
            float2 v0 = make_float2((float)(acc[mi][ni][0] + bq.x), (float)(acc[mi][ni][1] + bq.y));
            float2 v1 = make_float2((float)(acc[mi][ni][2] + bq.x), (float)(acc[mi][ni][3] + bq.y));
            *(float2*)(C + (size_t)rr * N_DIM + ncol + ni * 8) = v0;
            *(float2*)(C + (size_t)(rr + 8) * N_DIM + ncol + ni * 8) = v1;
        }
    }
}

// ---------------- launch ----------------
extern "C" void kernel_launch(void* const* d_in, const int* in_sizes, int n_in,
                              void* d_out, int out_size) {
    const float* x_q     = (const float*)d_in[0];   // [M, 512]
    const float* weight  = (const float*)d_in[1];   // [512, 512]
    const float* bias    = (const float*)d_in[2];   // [512]
    const float* scale_x = (const float*)d_in[3];   // [1]
    float* out = (float*)d_out;

    const int M = in_sizes[0] / K_DIM;
    const long long need = (long long)M * N_DIM + N_DIM;
    const int write_scale = ((long long)out_size >= need) ? 1 : 0;

    quant_weight_kernel<<<N_DIM, 256>>>(weight, bias, scale_x,
                                        out + (size_t)M * N_DIM, write_scale);

    const int n16 = M * K_DIM / 16;
    convert_x<<<(n16 + 255) / 256, 256>>>(x_q, n16);

    cudaFuncSetAttribute(gemm_imma, cudaFuncAttributeMaxDynamicSharedMemorySize, S_TOTAL);
    dim3 grid(N_DIM / BN, M / BM);
    gemm_imma<<<grid, 256, S_TOTAL>>>(out);
}

// round 8
// speedup vs baseline: 1.0146x; 1.0042x over previous
#include <cuda_runtime.h>
#include <cuda_bf16.h>
#include <cstdint>

#define K_DIM 512
#define N_DIM 512
#define BM 128
#define BN 128
#define M_MAX 65536

// ---------------- scratch (allocation-free) ----------------
// Tiled + swizzled images: tile t = 8KB = 128 rows x 64B, byte (r, b) at
// r*64 + (b ^ ((r*8)&0x30)). x tile index = mtile*8 + kchunk; w: ntile*8 + kchunk.
__device__ int  g_bqi[N_DIM];
__device__ __align__(16) char g_wq[N_DIM * K_DIM];
__device__ __align__(16) char g_xq[(size_t)M_MAX * K_DIM];

// ---------------- helpers ----------------
__device__ __forceinline__ uint32_t smem_u32(const void* p) {
    uint32_t a;
    asm("{ .reg .u64 t; cvta.to.shared.u64 t, %1; cvt.u32.u64 %0, t; }" : "=r"(a) : "l"(p));
    return a;
}
__device__ __forceinline__ void cp_bulk(uint32_t dst, const void* src, uint32_t bytes, uint32_t mbar) {
    asm volatile("cp.async.bulk.shared::cluster.global.mbarrier::complete_tx::bytes [%0], [%1], %2, [%3];"
                 :: "r"(dst), "l"(src), "r"(bytes), "r"(mbar) : "memory");
}
#define MBARRIER_INIT(addr, cnt) \
    asm volatile("mbarrier.init.shared.b64 [%0], %1;" :: "r"(addr), "r"(cnt) : "memory")
#define MBARRIER_EXPECT_TX(addr, tx) \
    asm volatile("mbarrier.arrive.expect_tx.shared.b64 _, [%0], %1;" :: "r"(addr), "r"(tx) : "memory")
#define MBARRIER_WAIT_PARITY(addr, par) do {                                        \
    uint32_t _m = (addr), _p = (par), _d;                                           \
    asm volatile("{ .reg .pred p; mbarrier.try_wait.parity.acquire.cta.shared::cta.b64 p, [%1], %2; selp.b32 %0,1,0,p; }" \
        : "=r"(_d) : "r"(_m), "r"(_p) : "memory");                                  \
    if (!_d) {                                                                      \
        asm volatile("{ .reg .pred P1; WL_%=: mbarrier.try_wait.parity.acquire.cta.shared::cta.b64 P1, [%0], %1, 0x989680;" \
                     " @P1 bra.uni WD_%=; bra.uni WL_%=; WD_%=: }"                  \
            :: "r"(_m), "r"(_p) : "memory");                                        \
    } } while (0)

__device__ __forceinline__ void ldmatrix_x4(uint32_t* r, uint32_t addr) {
    asm volatile("ldmatrix.sync.aligned.m8n8.x4.shared.b16 {%0,%1,%2,%3}, [%4];"
                 : "=r"(r[0]), "=r"(r[1]), "=r"(r[2]), "=r"(r[3]) : "r"(addr));
}
__device__ __forceinline__ void mma_s8(int* d, const uint32_t* a, uint32_t b0, uint32_t b1) {
    asm volatile("mma.sync.aligned.m16n8k32.row.col.s32.s8.s8.s32 "
                 "{%0,%1,%2,%3}, {%4,%5,%6,%7}, {%8,%9}, {%0,%1,%2,%3};"
                 : "+r"(d[0]), "+r"(d[1]), "+r"(d[2]), "+r"(d[3])
                 : "r"(a[0]), "r"(a[1]), "r"(a[2]), "r"(a[3]), "r"(b0), "r"(b1));
}
__device__ __forceinline__ uint32_t pack4(float a, float b, float c, float d) {
    int ia = __float2int_rn(a), ib = __float2int_rn(b);
    int ic = __float2int_rn(c), id = __float2int_rn(d);
    return (uint32_t)(ia & 255) | ((uint32_t)(ib & 255) << 8) |
           ((uint32_t)(ic & 255) << 16) | ((uint32_t)(id & 255) << 24);
}

// ---------------- x conversion: fp32 -> s8, tiled+swizzled; 16 elems/thread ----
__global__ void convert_x(const float* __restrict__ x, int n16) {
    int i = blockIdx.x * blockDim.x + threadIdx.x;
    if (i >= n16) return;
    const int m = i >> 5, j16 = i & 31;           // row, 16-elem group (k0 = j16*16)
    const float4* p = (const float4*)(x + (size_t)m * K_DIM + j16 * 16);
    float4 v0 = p[0], v1 = p[1], v2 = p[2], v3 = p[3];
    uint4 u;
    u.x = pack4(v0.x, v0.y, v0.z, v0.w);
    u.y = pack4(v1.x, v1.y, v1.z, v1.w);
    u.z = pack4(v2.x, v2.y, v2.z, v2.w);
    u.w = pack4(v3.x, v3.y, v3.z, v3.w);
    const int c = j16 >> 2, jj = j16 & 3;         // k-chunk, 16B slot in 64B row
    const int mt = m >> 7, r = m & 127;
    const size_t off = ((size_t)(mt * 8 + c) << 13) + r * 64 + ((jj * 16) ^ ((r * 8) & 0x30));
    *(uint4*)(g_xq + off) = u;
}

// ---------------- weight quantization (one block per output channel) ----------------
__global__ void quant_weight_kernel(const float* __restrict__ weight,
                                    const float* __restrict__ bias,
                                    const float* __restrict__ scale_x,
                                    float* __restrict__ scale_out_dst,
                                    int write_scale) {
    __shared__ float red[256];
    const int o = blockIdx.x;
    const float* wrow = weight + o * K_DIM;

    float m = 0.0f;
    for (int k = threadIdx.x; k < K_DIM; k += 256) m = fmaxf(m, fabsf(wrow[k]));
    red[threadIdx.x] = m;
    __syncthreads();
    for (int s = 128; s > 0; s >>= 1) {
        if (threadIdx.x < s) red[threadIdx.x] = fmaxf(red[threadIdx.x], red[threadIdx.x + s]);
        __syncthreads();
    }
    const float scale = fmaxf(red[0], 1e-8f) / 127.0f;
    const float inv_scale = 1.0f / scale;

    const int nt = o >> 7, rn = o & 127;
    const uint32_t rsw = (rn * 8) & 0x30;
    for (int k = threadIdx.x; k < K_DIM; k += 256) {
        float q = rintf(wrow[k] * inv_scale);             // round-half-even == jnp.round
        q = fminf(fmaxf(q, -128.0f), 127.0f);
        const size_t off = ((size_t)(nt * 8 + (k >> 6)) << 13) + rn * 64 + ((k & 63) ^ rsw);
        g_wq[off] = (char)(int)q;
    }
    if (threadIdx.x == 0) {
        const float so = scale * scale_x[0];
        float bq = rintf(bias[o] / so);
        bq = fminf(fmaxf(bq, -2147483520.0f), 2147483520.0f);
        g_bqi[o] = (int)bq;
        if (write_scale) scale_out_dst[o] = so;
    }
}

// ---------------- IMMA GEMM via TMA bulk loads ----------------
// 256 threads, 8 warps 2(M)x4(N); warp tile 64x32; 4 stages x 16KB (A 8KB + B 8KB),
// 8 one-shot mbarriers (parity 0), distance-3 prefetch, 1 issuing thread.
#define STAGE_SZ 16384
#define S_MBAR   65536
#define S_TOTAL  65664

__global__ __launch_bounds__(256, 2) void gemm_imma(float* __restrict__ C) {
    extern __shared__ __align__(1024) char smem[];
    const uint32_t sb = smem_u32(smem);
    const int tid = threadIdx.x, lane = tid & 31, w = tid >> 5;
    const int wm = w & 1, wn = w >> 1;

    const char* srcA = g_xq + ((size_t)blockIdx.y << 16);   // mtile*8 tiles of 8KB
    const char* srcB = g_wq + ((size_t)blockIdx.x << 16);   // ntile*8 tiles of 8KB

    // --- fragment lane addressing (64B rows, swizzle (row*8)&0x30)
    const uint32_t afr = wm * 64 + (lane & 15);
    const uint32_t afrx = (afr * 8) & 0x30;
    const uint32_t afkb = (lane >> 4) * 16;
    const uint32_t afbase = sb + afr * 64;
    const uint32_t bfr = wn * 32 + ((lane >> 4) << 3) + (lane & 7);
    const uint32_t bfrx = (bfr * 8) & 0x30;
    const uint32_t bfkb = ((lane >> 3) & 1) * 16;
    const uint32_t bfbase = sb + 8192 + bfr * 64;

    if (tid == 0) {
        #pragma unroll
        for (int s = 0; s < 8; s++) MBARRIER_INIT(sb + S_MBAR + s * 8, 1);
    }
    __syncthreads();

    if (tid == 0) {
        #pragma unroll
        for (int c = 0; c < 3; c++) {
            const uint32_t so = (uint32_t)c * STAGE_SZ;
            MBARRIER_EXPECT_TX(sb + S_MBAR + c * 8, 16384u);
            cp_bulk(sb + so,        srcA + (size_t)c * 8192, 8192u, sb + S_MBAR + c * 8);
            cp_bulk(sb + so + 8192, srcB + (size_t)c * 8192, 8192u, sb + S_MBAR + c * 8);
        }
    }

    int acc[4][4][4] = {};

    #pragma unroll 1
    for (int c = 0; c < 8; c++) {
        MBARRIER_WAIT_PARITY(sb + S_MBAR + c * 8, 0);
        __syncthreads();          // all reads of chunk c-1 done -> stage (c-1)&3 reusable

        if (tid == 0 && c < 5) {
            const int cn = c + 3;
            const uint32_t so1 = (uint32_t)(cn & 3) * STAGE_SZ;
            MBARRIER_EXPECT_TX(sb + S_MBAR + cn * 8, 16384u);
            cp_bulk(sb + so1,        srcA + (size_t)cn * 8192, 8192u, sb + S_MBAR + cn * 8);
            cp_bulk(sb + so1 + 8192, srcB + (size_t)cn * 8192, 8192u, sb + S_MBAR + cn * 8);
        }

        const uint32_t so = (uint32_t)(c & 3) * STAGE_SZ;
        #pragma unroll
        for (int kk = 0; kk < 2; kk++) {
            uint32_t af[4][4], bf[2][4];
            #pragma unroll
            for (int mi = 0; mi < 4; mi++)
                ldmatrix_x4(af[mi], afbase + so + mi * 1024 + ((kk * 32 + afkb) ^ afrx));
            #pragma unroll
            for (int pq = 0; pq < 2; pq++)
                ldmatrix_x4(bf[pq], bfbase + so + pq * 1024 + ((kk * 32 + bfkb) ^ bfrx));
            #pragma unroll
            for (int mi = 0; mi < 4; mi++)
                #pragma unroll
                for (int ni = 0; ni < 4; ni++)
                    mma_s8(acc[mi][ni], af[mi],
                           bf[ni >> 1][(ni & 1) * 2], bf[ni >> 1][(ni & 1) * 2 + 1]);
        }
    }

    // ---------------- epilogue: +bias(int), cvt to float, float2 stores
    const int mrow = blockIdx.y * BM + wm * 64 + (lane >> 2);
    const int ncol = blockIdx.x * BN + wn * 32 + (lane & 3) * 2;
    #pragma unroll
    for (int ni = 0; ni < 4; ni++) {
        const int2 bq = *(const int2*)&g_bqi[ncol + ni * 8];
        #pragma unroll
        for (int mi = 0; mi < 4; mi++) {
            const int rr = mrow + mi * 16;
            float2 v0 = make_float2((float)(acc[mi][ni][0] + bq.x), (float)(acc[mi][ni][1] + bq.y));
            float2 v1 = make_float2((float)(acc[mi][ni][2] + bq.x), (float)(acc[mi][ni][3] + bq.y));
            *(float2*)(C + (size_t)rr * N_DIM + ncol + ni * 8) = v0;
            *(float2*)(C + (size_t)(rr + 8) * N_DIM + ncol + ni * 8) = v1;
        }
    }
}

// ---------------- launch ----------------
extern "C" void kernel_launch(void* const* d_in, const int* in_sizes, int n_in,
                              void* d_out, int out_size) {
    const float* x_q     = (const float*)d_in[0];   // [M, 512]
    const float* weight  = (const float*)d_in[1];   // [512, 512]
    const float* bias    = (const float*)d_in[2];   // [512]
    const float* scale_x = (const float*)d_in[3];   // [1]
    float* out = (float*)d_out;

    const int M = in_sizes[0] / K_DIM;
    const long long need = (long long)M * N_DIM + N_DIM;
    const int write_scale = ((long long)out_size >= need) ? 1 : 0;

    quant_weight_kernel<<<N_DIM, 256>>>(weight, bias, scale_x,
                                        out + (size_t)M * N_DIM, write_scale);

    const int n16 = M * K_DIM / 16;
    convert_x<<<(n16 + 255) / 256, 256>>>(x_q, n16);

    cudaFuncSetAttribute(gemm_imma, cudaFuncAttributeMaxDynamicSharedMemorySize, S_TOTAL);
    dim3 grid(N_DIM / BN, M / BM);
    gemm_imma<<<grid, 256, S_TOTAL>>>(out);
}